// round 5
// baseline (speedup 1.0000x reference)
#include <cuda_runtime.h>

// ReceptiveFieldLayer: J=4, R=10, pad=3.
// out[b,c,i,j] = relu(max over 2-3 taps/axis of feat[b,x,y,c]), c in {0,1,2}
// Input : [16, 256, 256, 64] f32 NHWC.  Output: [16, 3, 1024, 1024] f32.
//
// CTA = 16 output rows x 1024 cols x 3 ch (one band). Patch: 6 feature rows
// x 258 cols x 3 ch in SMEM (zero-padded). Thread q owns output cols
// 4q..4q+3 for ALL 16 rows: per-shared-row column maxes computed once,
// pairwise row maxes shared across adjacent row-groups. Streaming STG.128.

#define SH_W 258
#define NPOS (6 * SH_W)   // 1548

__global__ __launch_bounds__(256)
void rf_band_kernel(const float* __restrict__ in, float* __restrict__ out) {
    __shared__ float sh[3][6][SH_W];

    const int i0 = blockIdx.x * 16;      // output row base
    const int b  = blockIdx.y;
    const int fq = i0 >> 2;              // feature row base quotient
    const int tid = threadIdx.x;

    // ---- Load 3-ch, 6-row x 258-col feature patch (zero-padded) ----
    for (int pos = tid; pos < NPOS; pos += 256) {
        int sx = pos / SH_W;             // 0..5 -> feature row fq-1+sx
        int sy = pos - sx * SH_W;        // 0..257 -> feature col sy-1
        int fx = fq - 1 + sx;
        int fy = sy - 1;
        float x = 0.f, y = 0.f, z = 0.f;
        if ((unsigned)fx < 256u && (unsigned)fy < 256u) {
            const float4 v = __ldg(reinterpret_cast<const float4*>(
                in + ((((size_t)b * 256 + fx) * 256 + fy) << 6)));
            x = v.x; y = v.y; z = v.z;
        }
        sh[0][sx][sy] = x;
        sh[1][sx][sy] = y;
        sh[2][sx][sy] = z;
    }
    __syncthreads();

    const int q = tid;                   // col group: output cols 4q..4q+3

    #pragma unroll
    for (int ch = 0; ch < 3; ch++) {
        // per-shared-row column maxes: a={q,q+1}, b={q+1,q+2}, c={q,q+1,q+2}
        float ca[6], cb[6], cc[6];
        #pragma unroll
        for (int r = 0; r < 6; r++) {
            float x0 = sh[ch][r][q], x1 = sh[ch][r][q + 1], x2 = sh[ch][r][q + 2];
            ca[r] = fmaxf(x0, x1);
            cb[r] = fmaxf(x1, x2);
            cc[r] = fmaxf(ca[r], x2);
        }
        // pairwise row maxes m[r] = max over shared rows {r, r+1}
        float ma[5], mb[5], mc[5];
        #pragma unroll
        for (int r = 0; r < 5; r++) {
            ma[r] = fmaxf(ca[r], ca[r + 1]);
            mb[r] = fmaxf(cb[r], cb[r + 1]);
            mc[r] = fmaxf(cc[r], cc[r + 1]);
        }

        float* obase = out + ((((size_t)b * 3 + ch) * 1024) + (size_t)i0) * 1024
                       + (size_t)q * 4;

        #pragma unroll
        for (int rg = 0; rg < 4; rg++) {
            // rows: k=0 -> shared {rg,rg+1}; k=1,2 -> {rg..rg+2}; k=3 -> {rg+1,rg+2}
            float t0a = fmaxf(ma[rg], 0.f);
            float t0b = fmaxf(mb[rg], 0.f);
            float t0c = fmaxf(mc[rg], 0.f);
            float t1a = fmaxf(fmaxf(ma[rg], ca[rg + 2]), 0.f);
            float t1b = fmaxf(fmaxf(mb[rg], cb[rg + 2]), 0.f);
            float t1c = fmaxf(fmaxf(mc[rg], cc[rg + 2]), 0.f);
            float t3a = fmaxf(ma[rg + 1], 0.f);
            float t3b = fmaxf(mb[rg + 1], 0.f);
            float t3c = fmaxf(mc[rg + 1], 0.f);

            // within 4-col group: k'=0 -> a, k'=1,2 -> c, k'=3 -> b
            float4 v0 = make_float4(t0a, t0c, t0c, t0b);
            float4 v1 = make_float4(t1a, t1c, t1c, t1b);
            float4 v3 = make_float4(t3a, t3c, t3c, t3b);

            float4* o = reinterpret_cast<float4*>(obase + (size_t)(rg * 4) * 1024);
            __stcs(o,        v0);
            __stcs(o +  256, v1);   // +1024 floats
            __stcs(o +  512, v1);
            __stcs(o +  768, v3);
        }
    }
}

extern "C" void kernel_launch(void* const* d_in, const int* in_sizes, int n_in,
                              void* d_out, int out_size) {
    const float* in = (const float*)d_in[0];
    float* out = (float*)d_out;
    dim3 grid(1024 / 16, 16);   // 64 bands x 16 batches = 1024 CTAs
    rf_band_kernel<<<grid, 256>>>(in, out);
}

// round 6
// speedup vs baseline: 1.1767x; 1.1767x over previous
#include <cuda_runtime.h>

// ReceptiveFieldLayer: J=4, R=10, pad=3.
// out[b,c,i,j] = relu(max over 2-3 taps/axis of feat[b,x,y,c]), c in {0,1,2}
// Input : [16, 256, 256, 64] f32 NHWC.  Output: [16, 3, 1024, 1024] f32.
//
// R1 scheme, 64x128 tile / 512 threads (halo bytes -10% vs 32x128):
//  - patch: 18 feature rows x 34 cols x 3 ch (7.3 KB smem), zero-padded.
//  - thread (rg,q): 4x4 output block from a 3x3 shared patch, x3 channels.
//  - streaming STG.128 writes (__stcs), 2048 CTAs.

#define TILE_H 64
#define TILE_W 128
#define SH_H 18
#define SH_W 34
#define NPOS (SH_H * SH_W)   // 612

__global__ __launch_bounds__(512)
void rf_scatter_max_kernel(const float* __restrict__ in, float* __restrict__ out) {
    __shared__ float sh[3][SH_H][SH_W];

    const int b  = blockIdx.z;
    const int i0 = blockIdx.y * TILE_H;   // output row base
    const int j0 = blockIdx.x * TILE_W;   // output col base
    const int fq = i0 >> 2;               // feature row base quotient
    const int gq = j0 >> 2;

    const int tid = threadIdx.x;

    // ---- Load 3-channel feature patch (zero-padded outside [0,256)) ----
    for (int pos = tid; pos < NPOS; pos += 512) {
        int sx = pos / SH_W;
        int sy = pos - sx * SH_W;
        int fx = fq - 1 + sx;
        int fy = gq - 1 + sy;
        float x = 0.f, y = 0.f, z = 0.f;
        if ((unsigned)fx < 256u && (unsigned)fy < 256u) {
            const float4 v = __ldg(reinterpret_cast<const float4*>(
                in + ((((size_t)b * 256 + fx) * 256 + fy) << 6)));
            x = v.x; y = v.y; z = v.z;
        }
        sh[0][sx][sy] = x;
        sh[1][sx][sy] = y;
        sh[2][sx][sy] = z;
    }
    __syncthreads();

    // ---- Each thread: 4x4 output block from a 3x3 shared patch ----
    const int q  = tid & 31;   // col group: output cols j0+4q..+3, shared cols q..q+2
    const int rg = tid >> 5;   // row group 0..15: output rows i0+4rg..+3, shared rows rg..rg+2

    #pragma unroll
    for (int ch = 0; ch < 3; ch++) {
        float a00 = sh[ch][rg    ][q], a01 = sh[ch][rg    ][q + 1], a02 = sh[ch][rg    ][q + 2];
        float a10 = sh[ch][rg + 1][q], a11 = sh[ch][rg + 1][q + 1], a12 = sh[ch][rg + 1][q + 2];
        float a20 = sh[ch][rg + 2][q], a21 = sh[ch][rg + 2][q + 1], a22 = sh[ch][rg + 2][q + 2];

        // column maxes per shared row: a={q,q+1}, b={q+1,q+2}, c={q,q+1,q+2}
        float c0a = fmaxf(a00, a01), c0b = fmaxf(a01, a02), c0c = fmaxf(c0a, a02);
        float c1a = fmaxf(a10, a11), c1b = fmaxf(a11, a12), c1c = fmaxf(c1a, a12);
        float c2a = fmaxf(a20, a21), c2b = fmaxf(a21, a22), c2c = fmaxf(c2a, a22);

        // row combos (relu folded): row 0 -> {s0,s1}; rows 1,2 -> {s0,s1,s2}; row 3 -> {s1,s2}
        float r01_a  = fmaxf(fmaxf(c0a, c1a), 0.f);
        float r01_c  = fmaxf(fmaxf(c0c, c1c), 0.f);
        float r01_b  = fmaxf(fmaxf(c0b, c1b), 0.f);
        float r012_a = fmaxf(r01_a, c2a);
        float r012_c = fmaxf(r01_c, c2c);
        float r012_b = fmaxf(r01_b, c2b);
        float r12_a  = fmaxf(fmaxf(c1a, c2a), 0.f);
        float r12_c  = fmaxf(fmaxf(c1c, c2c), 0.f);
        float r12_b  = fmaxf(fmaxf(c1b, c2b), 0.f);

        // within 4-col group: k'=0 -> a, k'=1,2 -> c, k'=3 -> b
        float4 v0 = make_float4(r01_a,  r01_c,  r01_c,  r01_b);
        float4 v1 = make_float4(r012_a, r012_c, r012_c, r012_b);
        float4 v3 = make_float4(r12_a,  r12_c,  r12_c,  r12_b);

        size_t base = ((((size_t)b * 3 + ch) * 1024) + (size_t)(i0 + rg * 4)) * 1024
                      + (size_t)(j0 + q * 4);
        float4* o = reinterpret_cast<float4*>(out + base);
        __stcs(o,        v0);
        __stcs(o +  256, v1);   // +1024 floats = +256 float4
        __stcs(o +  512, v1);
        __stcs(o +  768, v3);
    }
}

extern "C" void kernel_launch(void* const* d_in, const int* in_sizes, int n_in,
                              void* d_out, int out_size) {
    const float* in = (const float*)d_in[0];
    float* out = (float*)d_out;
    dim3 grid(1024 / TILE_W, 1024 / TILE_H, 16);   // (8, 16, 16) = 2048 CTAs
    rf_scatter_max_kernel<<<grid, 512>>>(in, out);
}